// round 6
// baseline (speedup 1.0000x reference)
#include <cuda_runtime.h>
#include <stdint.h>

#define BATCH 32
#define CIN   128
#define HH    56
#define WW    56
#define COUT  256
#define HP    58
#define NPIX  (HH*WW)            // 3136
#define IMGB  (HP*HP*CIN)

// ---------------- scratch (device globals) ----------------------------------
__device__ int8_t g_qx[BATCH*HP*HP*CIN];   // padded NHWC int8
__device__ int8_t g_qw[9*COUT*CIN];        // [tap][co][ci]
__device__ float  g_px[1024];              // partial amax (x)
__device__ float  g_pw[64];                // partial amax (w)
__device__ float  g_scale_x, g_dq;

// ---------------- helpers -----------------------------------------------------
__device__ __forceinline__ uint32_t smem_u32(const void* p) {
    uint32_t a;
    asm("{ .reg .u64 t; cvta.to.shared.u64 t, %1; cvt.u32.u64 %0, t; }" : "=r"(a) : "l"(p));
    return a;
}
#define SW128(o) ((o) ^ (((o) >> 3) & 0x70))

__device__ __forceinline__ void cp16(uint32_t dst, const void* src) {
    asm volatile("cp.async.cg.shared.global [%0], [%1], 16;" :: "r"(dst), "l"(src) : "memory");
}
#define CP_COMMIT()  asm volatile("cp.async.commit_group;" ::: "memory")
#define CP_WAIT(n)   asm volatile("cp.async.wait_group %0;" :: "n"(n) : "memory")

__device__ __forceinline__ unsigned lds32(uint32_t a) {
    unsigned v; asm volatile("ld.shared.b32 %0, [%1];" : "=r"(v) : "r"(a)); return v;
}

__device__ __forceinline__ void mma16832(int* d, const unsigned* a, const unsigned* b) {
    asm volatile("mma.sync.aligned.m16n8k32.row.col.s32.s8.s8.s32 "
        "{%0,%1,%2,%3}, {%4,%5,%6,%7}, {%8,%9}, {%0,%1,%2,%3};"
        : "+r"(d[0]), "+r"(d[1]), "+r"(d[2]), "+r"(d[3])
        : "r"(a[0]), "r"(a[1]), "r"(a[2]), "r"(a[3]), "r"(b[0]), "r"(b[1]));
}

__device__ __forceinline__ float warp_red_max(float m) {
    #pragma unroll
    for (int o = 16; o; o >>= 1) m = fmaxf(m, __shfl_xor_sync(0xffffffffu, m, o));
    return m;
}

// ---------------- 0: partial amax --------------------------------------------
__global__ void k_part(const float4* __restrict__ x, const float4* __restrict__ w) {
    int blk = blockIdx.x;
    const float4* p; int n4, stride, start;
    if (blk < 1024) { p = x; n4 = BATCH*CIN*HH*WW/4; start = blk*256 + threadIdx.x; stride = 1024*256; }
    else            { p = w; n4 = COUT*CIN*9/4;      start = (blk-1024)*256 + threadIdx.x; stride = 64*256; }
    float m = 0.f;
    for (int i = start; i < n4; i += stride) {
        float4 v = p[i];
        m = fmaxf(m, fmaxf(fmaxf(fabsf(v.x), fabsf(v.y)), fmaxf(fabsf(v.z), fabsf(v.w))));
    }
    m = warp_red_max(m);
    __shared__ float sm[8];
    int lane = threadIdx.x & 31, wid = threadIdx.x >> 5;
    if (lane == 0) sm[wid] = m;
    __syncthreads();
    if (wid == 0) {
        m = (lane < 8) ? sm[lane] : 0.f;
        m = warp_red_max(m);
        if (lane == 0) { if (blk < 1024) g_px[blk] = m; else g_pw[blk-1024] = m; }
    }
}

// ---------------- 1: finalize scales + quantize weights ----------------------
__global__ void k_quant_w(const float* __restrict__ wt) {
    __shared__ float s_sw;
    {
        float mx = 0.f, mw = 0.f;
        for (int i = threadIdx.x; i < 1024; i += blockDim.x) mx = fmaxf(mx, g_px[i]);
        if (threadIdx.x < 64) mw = g_pw[threadIdx.x];
        mx = warp_red_max(mx); mw = warp_red_max(mw);
        __shared__ float smx[8], smw[8];
        int lane = threadIdx.x & 31, wid = threadIdx.x >> 5;
        if (lane == 0) { smx[wid] = mx; smw[wid] = mw; }
        __syncthreads();
        if (threadIdx.x == 0) {
            float ax = 0.f, aw = 0.f;
            #pragma unroll
            for (int i = 0; i < 8; i++) { ax = fmaxf(ax, smx[i]); aw = fmaxf(aw, smw[i]); }
            float sx = __fdiv_rn(127.0f, ax);
            float sw = __fdiv_rn(127.0f, aw);
            s_sw = sw;
            if (blockIdx.x == 0) {
                g_scale_x = sx;
                g_dq = __fdiv_rn(1.0f, __fmul_rn(sx, sw));
            }
        }
        __syncthreads();
    }
    float sc = s_sw;
    const int n = 9*COUT*CIN;
    for (int o = blockIdx.x*blockDim.x + threadIdx.x; o < n; o += gridDim.x*blockDim.x) {
        int ci  = o & 127;
        int co  = (o >> 7) & 255;
        int tap = o >> 15;
        float q = rintf(wt[(co*CIN + ci)*9 + tap] * sc);
        q = fminf(fmaxf(q, -127.f), 127.f);
        g_qw[o] = (int8_t)q;
    }
}

// ---------------- 2: quantize x into padded NHWC ------------------------------
__global__ void k_quant_x(const float* __restrict__ x) {
    int b = blockIdx.x / HP, hp = blockIdx.x % HP;
    int8_t* dst = g_qx + ((size_t)b*HP + hp)*HP*CIN;
    if (hp == 0 || hp == HP-1) {
        for (int e = threadIdx.x; e < HP*CIN/16; e += blockDim.x)
            ((int4*)dst)[e] = make_int4(0,0,0,0);
        return;
    }
    int h = hp - 1;
    __shared__ int8_t s[CIN][60];
    float sc = g_scale_x;
    const float* base = x + ((size_t)b*CIN*HH + h)*WW;
    for (int e = threadIdx.x; e < CIN*WW; e += blockDim.x) {
        int c = e / WW, w = e - c*WW;
        float q = rintf(base[(size_t)c*HH*WW + w] * sc);
        q = fminf(fmaxf(q, -127.f), 127.f);
        s[c][w] = (int8_t)q;
    }
    __syncthreads();
    for (int e = threadIdx.x; e < HP*CIN; e += blockDim.x) {
        int wp = e >> 7, c = e & 127;
        dst[e] = (wp == 0 || wp == HP-1) ? (int8_t)0 : s[c][wp-1];
    }
}

// ---------------- 3: PERSISTENT hybrid conv -----------------------------------
// 296 CTAs, 2/SM (full RF). bid<148 -> IMMA role (co 0-127), else dp4a role
// (co 128-255). bid b and b+148 map to the SAME SM => every SM runs exactly
// one IMMA CTA (tensor pipe) + one dp4a CTA (IMAD pipe) concurrently.
#define STAGE_B 32768
#define SMEM_TOTAL (2*STAGE_B)
#define N_IMMA_ITEMS (25*BATCH)     // 800: 128-px strips x co 0-127
#define N_DP4A_ITEMS (49*BATCH)     // 1568: 8x8-px tiles x co 128-255

__global__ void __launch_bounds__(256, 2) k_conv(const float* __restrict__ bias,
                                                 float* __restrict__ out) {
    extern __shared__ char smem[];
    int tid = threadIdx.x;
    int bid = blockIdx.x;

    if (bid < 148) {
        // ================= IMMA role: 128 px x couts 0..127 =================
        uint32_t sb = smem_u32(smem);
        float* s_out = (float*)smem;
        int wid = tid >> 5, lane = tid & 31;
        int wm = wid & 3, wn = wid >> 2;          // 4 x 2 warp grid
        int g = lane >> 2, tg = lane & 3;
        int tg8 = tid >> 3, j16 = (tid & 7) * 16;
        const int8_t* wb = g_qw + tg8*CIN + j16;  // couts 0..127
        int rr = tid >> 7, px = tid & 127;

        for (int item = bid; item < N_IMMA_ITEMS; item += 148) {
            int bimg = item / 25, it = item - bimg*25;
            int p0 = it * 128;

            int aoff[4];
            #pragma unroll
            for (int k = 0; k < 4; k++) {
                int p = min(p0 + k*32 + tg8, NPIX-1);
                int h = p / WW, w = p - h*WW;
                aoff[k] = (h*HP + w)*CIN + j16;
            }
            const int8_t* qb = g_qx + (size_t)bimg * IMGB;

            int acc[2][8][4];
            #pragma unroll
            for (int mt = 0; mt < 2; mt++)
                #pragma unroll
                for (int nt = 0; nt < 8; nt++)
                    #pragma unroll
                    for (int r = 0; r < 4; r++) acc[mt][nt][r] = 0;

            {
                uint32_t stgA = sb, stgB = sb + 16384;
                #pragma unroll
                for (int k = 0; k < 4; k++) {
                    cp16(stgA + SW128((k*32 + tg8)*128 + j16), qb + aoff[k]);
                    cp16(stgB + SW128((k*32 + tg8)*128 + j16), wb + (size_t)k*32*CIN);
                }
                CP_COMMIT();
            }

            for (int ch = 0; ch < 9; ch++) {
                int st = ch & 1;
                if (ch < 8) {
                    int nc = ch + 1;
                    int dh = nc / 3, dw = nc - dh*3;
                    int doff = (dh*HP + dw)*CIN;
                    uint32_t stgA = sb + ((nc & 1) ? STAGE_B : 0), stgB = stgA + 16384;
                    const int8_t* wsrc = wb + (size_t)nc*COUT*CIN;
                    #pragma unroll
                    for (int k = 0; k < 4; k++) {
                        cp16(stgA + SW128((k*32 + tg8)*128 + j16), qb + aoff[k] + doff);
                        cp16(stgB + SW128((k*32 + tg8)*128 + j16), wsrc + (size_t)k*32*CIN);
                    }
                    CP_COMMIT();
                    CP_WAIT(1);
                } else {
                    CP_WAIT(0);
                }
                __syncthreads();

                uint32_t stgA = sb + st*STAGE_B, stgB = stgA + 16384;
                #pragma unroll
                for (int ks = 0; ks < 4; ks++) {
                    unsigned bf[8][2];
                    #pragma unroll
                    for (int nt = 0; nt < 8; nt++) {
                        uint32_t base = (wn*64 + nt*8 + g)*128 + ks*32 + tg*4;
                        bf[nt][0] = lds32(stgB + SW128(base));
                        bf[nt][1] = lds32(stgB + SW128(base + 16));
                    }
                    #pragma unroll
                    for (int mt = 0; mt < 2; mt++) {
                        unsigned af[4];
                        uint32_t base = (wm*32 + mt*16 + g)*128 + ks*32 + tg*4;
                        af[0] = lds32(stgA + SW128(base));
                        af[1] = lds32(stgA + SW128(base + 8*128));
                        af[2] = lds32(stgA + SW128(base + 16));
                        af[3] = lds32(stgA + SW128(base + 8*128 + 16));
                        #pragma unroll
                        for (int nt = 0; nt < 8; nt++)
                            mma16832(acc[mt][nt], af, bf[nt]);
                    }
                }
                __syncthreads();
            }

            float dq = g_dq;
            bool pv = (p0 + px) < NPIX;
            float* obase = out + (size_t)bimg*COUT*NPIX + p0 + px;

            #pragma unroll
            for (int pass = 0; pass < 2; pass++) {
                if (wn == pass) {
                    #pragma unroll
                    for (int mt = 0; mt < 2; mt++) {
                        int px0 = wm*32 + mt*16 + g;
                        #pragma unroll
                        for (int nt = 0; nt < 8; nt++) {
                            int cl = nt*8 + tg*2;
                            s_out[cl*132 + px0]         = (float)acc[mt][nt][0] * dq;
                            s_out[(cl+1)*132 + px0]     = (float)acc[mt][nt][1] * dq;
                            s_out[cl*132 + px0 + 8]     = (float)acc[mt][nt][2] * dq;
                            s_out[(cl+1)*132 + px0 + 8] = (float)acc[mt][nt][3] * dq;
                        }
                    }
                }
                __syncthreads();
                if (pv) {
                    #pragma unroll 8
                    for (int itr = 0; itr < 32; itr++) {
                        int row = itr*2 + rr;
                        int co = pass*64 + row;
                        obase[(size_t)co * NPIX] = s_out[row*132 + px] + __ldg(&bias[co]);
                    }
                }
                __syncthreads();
            }
        }
    } else {
        // ================= dp4a role: 8x8 px x couts 128..255 =================
        int cb = bid - 148;
        int* s_x = (int*)smem;                // [32][10][12] = 15360B
        int* s_w = (int*)(smem + 15360);      // [32][129]    = 16512B
        int py = tid & 7, cg = tid >> 3;      // 8 px-rows x 32 cout-groups(4)
        const int* qw = (const int*)g_qw;

        float bv[4];
        #pragma unroll
        for (int c = 0; c < 4; c++) bv[c] = __ldg(&bias[128 + cg*4 + c]);
        float dq = g_dq;

        for (int item = cb; item < N_DP4A_ITEMS; item += 148) {
            int bimg = item / 49, dt = item - bimg*49;
            int ty = dt / 7, tx = dt - ty*7;
            int gx0 = tx*8, gy0 = ty*8;
            const int* qx = (const int*)(g_qx + (size_t)bimg*IMGB);

            __syncthreads();   // protect s_x/s_w from previous item's readers
            for (int idx = tid; idx < 3200; idx += 256) {
                int k = idx & 31, pos = idx >> 5;
                int ph = pos / 10, pw = pos - ph*10;
                s_x[(k*10 + ph)*12 + pw] = qx[((gy0+ph)*HP + (gx0+pw))*32 + k];
            }

            int acc[8][4];
            #pragma unroll
            for (int j = 0; j < 8; j++)
                #pragma unroll
                for (int c = 0; c < 4; c++) acc[j][c] = 0;

            for (int tap = 0; tap < 9; tap++) {
                __syncthreads();
                const int* wsrc = qw + (tap*COUT + 128)*32;   // couts 128..255
                for (int idx = tid; idx < 4096; idx += 256) {
                    int k = idx & 31, co2 = idx >> 5;
                    s_w[k*129 + co2] = wsrc[co2*32 + k];
                }
                __syncthreads();
                int kh = tap / 3, kw = tap - kh*3;
                #pragma unroll 4
                for (int k = 0; k < 32; k++) {
                    int xv[8], wv[4];
                    #pragma unroll
                    for (int j = 0; j < 8; j++) xv[j] = s_x[(k*10 + py + kh)*12 + j + kw];
                    #pragma unroll
                    for (int c = 0; c < 4; c++) wv[c] = s_w[k*129 + cg*4 + c];
                    #pragma unroll
                    for (int j = 0; j < 8; j++)
                        #pragma unroll
                        for (int c = 0; c < 4; c++)
                            acc[j][c] = __dp4a(xv[j], wv[c], acc[j][c]);
                }
            }

            int gy = gy0 + py;
            #pragma unroll
            for (int c = 0; c < 4; c++) {
                int co = 128 + cg*4 + c;
                float t[8];
                #pragma unroll
                for (int j = 0; j < 8; j++) t[j] = (float)acc[j][c] * dq + bv[c];
                float* op = out + (((size_t)bimg*COUT + co)*HH + gy)*WW + gx0;
                ((float4*)op)[0] = make_float4(t[0], t[1], t[2], t[3]);
                ((float4*)op)[1] = make_float4(t[4], t[5], t[6], t[7]);
            }
        }
    }
}

// ---------------- launch ------------------------------------------------------
extern "C" void kernel_launch(void* const* d_in, const int* in_sizes, int n_in,
                              void* d_out, int out_size) {
    const float* x    = (const float*)d_in[0];
    const float* wt   = (const float*)d_in[1];
    const float* bias = (const float*)d_in[2];
    float* out = (float*)d_out;

    cudaFuncSetAttribute(k_conv, cudaFuncAttributeMaxDynamicSharedMemorySize, SMEM_TOTAL);

    k_part<<<1088, 256>>>((const float4*)x, (const float4*)wt);   // idx 0
    k_quant_w<<<288, 256>>>(wt);                                  // idx 1
    k_quant_x<<<BATCH*HP, 256>>>(x);                              // idx 2
    k_conv<<<296, 256, SMEM_TOTAL>>>(bias, out);                  // idx 3 (ncu captures this)
    (void)in_sizes; (void)n_in; (void)out_size;
}

// round 8
// speedup vs baseline: 1.1967x; 1.1967x over previous
#include <cuda_runtime.h>
#include <stdint.h>

#define BATCH 32
#define CIN   128
#define HH    56
#define WW    56
#define COUT  256
#define HP    58
#define NPIX  (HH*WW)            // 3136
#define IMGB  (HP*HP*CIN)

// ---------------- scratch (device globals) ----------------------------------
__device__ int8_t g_qx[BATCH*HP*HP*CIN];   // padded NHWC int8
__device__ int8_t g_qw[9*COUT*CIN];        // [tap][co][ci]
__device__ float  g_px[1024];
__device__ float  g_pw[64];
__device__ float  g_scale_x, g_dq;

// ---------------- helpers -----------------------------------------------------
__device__ __forceinline__ uint32_t smem_u32(const void* p) {
    uint32_t a;
    asm("{ .reg .u64 t; cvta.to.shared.u64 t, %1; cvt.u32.u64 %0, t; }" : "=r"(a) : "l"(p));
    return a;
}
#define SW128(o) ((o) ^ (((o) >> 3) & 0x70))

__device__ __forceinline__ void cp16(uint32_t dst, const void* src) {
    asm volatile("cp.async.cg.shared.global [%0], [%1], 16;" :: "r"(dst), "l"(src) : "memory");
}
#define CP_COMMIT()  asm volatile("cp.async.commit_group;" ::: "memory")
#define CP_WAIT(n)   asm volatile("cp.async.wait_group %0;" :: "n"(n) : "memory")

__device__ __forceinline__ unsigned lds32(uint32_t a) {
    unsigned v; asm volatile("ld.shared.b32 %0, [%1];" : "=r"(v) : "r"(a)); return v;
}

__device__ __forceinline__ void mma16832(int* d, const unsigned* a, const unsigned* b) {
    asm volatile("mma.sync.aligned.m16n8k32.row.col.s32.s8.s8.s32 "
        "{%0,%1,%2,%3}, {%4,%5,%6,%7}, {%8,%9}, {%0,%1,%2,%3};"
        : "+r"(d[0]), "+r"(d[1]), "+r"(d[2]), "+r"(d[3])
        : "r"(a[0]), "r"(a[1]), "r"(a[2]), "r"(a[3]), "r"(b[0]), "r"(b[1]));
}

__device__ __forceinline__ float warp_red_max(float m) {
    #pragma unroll
    for (int o = 16; o; o >>= 1) m = fmaxf(m, __shfl_xor_sync(0xffffffffu, m, o));
    return m;
}

// ---------------- 0: partial amax --------------------------------------------
__global__ void k_part(const float4* __restrict__ x, const float4* __restrict__ w) {
    int blk = blockIdx.x;
    const float4* p; int n4, stride, start;
    if (blk < 1024) { p = x; n4 = BATCH*CIN*HH*WW/4; start = blk*256 + threadIdx.x; stride = 1024*256; }
    else            { p = w; n4 = COUT*CIN*9/4;      start = (blk-1024)*256 + threadIdx.x; stride = 64*256; }
    float m = 0.f;
    for (int i = start; i < n4; i += stride) {
        float4 v = p[i];
        m = fmaxf(m, fmaxf(fmaxf(fabsf(v.x), fabsf(v.y)), fmaxf(fabsf(v.z), fabsf(v.w))));
    }
    m = warp_red_max(m);
    __shared__ float sm[8];
    int lane = threadIdx.x & 31, wid = threadIdx.x >> 5;
    if (lane == 0) sm[wid] = m;
    __syncthreads();
    if (wid == 0) {
        m = (lane < 8) ? sm[lane] : 0.f;
        m = warp_red_max(m);
        if (lane == 0) { if (blk < 1024) g_px[blk] = m; else g_pw[blk-1024] = m; }
    }
}

// ---------------- 1: finalize scales + quantize weights ----------------------
__global__ void k_quant_w(const float* __restrict__ wt) {
    __shared__ float s_sw;
    {
        float mx = 0.f, mw = 0.f;
        for (int i = threadIdx.x; i < 1024; i += blockDim.x) mx = fmaxf(mx, g_px[i]);
        if (threadIdx.x < 64) mw = g_pw[threadIdx.x];
        mx = warp_red_max(mx); mw = warp_red_max(mw);
        __shared__ float smx[8], smw[8];
        int lane = threadIdx.x & 31, wid = threadIdx.x >> 5;
        if (lane == 0) { smx[wid] = mx; smw[wid] = mw; }
        __syncthreads();
        if (threadIdx.x == 0) {
            float ax = 0.f, aw = 0.f;
            #pragma unroll
            for (int i = 0; i < 8; i++) { ax = fmaxf(ax, smx[i]); aw = fmaxf(aw, smw[i]); }
            float sx = __fdiv_rn(127.0f, ax);
            float sw = __fdiv_rn(127.0f, aw);
            s_sw = sw;
            if (blockIdx.x == 0) {
                g_scale_x = sx;
                g_dq = __fdiv_rn(1.0f, __fmul_rn(sx, sw));
            }
        }
        __syncthreads();
    }
    float sc = s_sw;
    const int n = 9*COUT*CIN;
    for (int o = blockIdx.x*blockDim.x + threadIdx.x; o < n; o += gridDim.x*blockDim.x) {
        int ci  = o & 127;
        int co  = (o >> 7) & 255;
        int tap = o >> 15;
        float q = rintf(wt[(co*CIN + ci)*9 + tap] * sc);
        q = fminf(fmaxf(q, -127.f), 127.f);
        g_qw[o] = (int8_t)q;
    }
}

// ---------------- 2: quantize x into padded NHWC ------------------------------
__global__ void k_quant_x(const float* __restrict__ x) {
    int b = blockIdx.x / HP, hp = blockIdx.x % HP;
    int8_t* dst = g_qx + ((size_t)b*HP + hp)*HP*CIN;
    if (hp == 0 || hp == HP-1) {
        for (int e = threadIdx.x; e < HP*CIN/16; e += blockDim.x)
            ((int4*)dst)[e] = make_int4(0,0,0,0);
        return;
    }
    int h = hp - 1;
    __shared__ int8_t s[CIN][60];
    float sc = g_scale_x;
    const float* base = x + ((size_t)b*CIN*HH + h)*WW;
    for (int e = threadIdx.x; e < CIN*WW; e += blockDim.x) {
        int c = e / WW, w = e - c*WW;
        float q = rintf(base[(size_t)c*HH*WW + w] * sc);
        q = fminf(fmaxf(q, -127.f), 127.f);
        s[c][w] = (int8_t)q;
    }
    __syncthreads();
    for (int e = threadIdx.x; e < HP*CIN; e += blockDim.x) {
        int wp = e >> 7, c = e & 127;
        dst[e] = (wp == 0 || wp == HP-1) ? (int8_t)0 : s[c][wp-1];
    }
}

// ---------------- 3: FUSED dual-pipe conv ------------------------------------
// CTA: 128-px strip x 256 couts, 512 threads, 1 CTA/SM (full RF).
// Every warp interleaves: IMMA 32px x 32co (couts 0-127, tensor pipe)
//                       + dp4a 32px x 32co (couts 128-255, fma pipe),
// both consuming the SAME staged A tile. Stage = A(16K)+Bi(16K)+Bd(16K),
// double-buffered via cp.async.
#define STAGE 49152
#define SMEM_TOTAL 98304

__global__ void __launch_bounds__(512, 1) k_conv(const float* __restrict__ bias,
                                                 float* __restrict__ out) {
    extern __shared__ char smem[];
    uint32_t sb = smem_u32(smem);
    float* s_f = (float*)smem;                  // epilogue: [128co][133px] floats

    int tid = threadIdx.x;
    int wid = tid >> 5, lane = tid & 31;
    // IMMA ids (4m x 4n warp grid, validated round-4 mapping)
    int wm = wid & 3, wn = wid >> 2;
    int g = lane >> 2, tg = lane & 3;
    // dp4a ids (8px x 4co within warp; lane = pl + 8*cl)
    int pl = lane & 7, cl = lane >> 3;

    int strip = blockIdx.x, bimg = blockIdx.y;
    int p0 = strip * 128;

    // producer coords: thread t -> row t>>2, col (t&3)*32 (+16), for A/Bi/Bd
    int row = tid >> 2, col = (tid & 3) << 5;
    int p = min(p0 + row, NPIX-1);
    int ph = p / WW, pw = p - ph*WW;
    int aoff = (ph*HP + pw)*CIN + col;
    const int8_t* qb  = g_qx + (size_t)bimg * IMGB;
    const int8_t* wbi = g_qw + row*CIN + col;          // couts 0..127
    const int8_t* wbd = g_qw + (128 + row)*CIN + col;  // couts 128..255
    uint32_t d0 = SW128(row*128 + col), d1 = SW128(row*128 + col + 16);

    int acci[2][4][4];   // IMMA accum
    int accd[4][8];      // dp4a accum: [px m][co c]
    #pragma unroll
    for (int mt = 0; mt < 2; mt++)
        #pragma unroll
        for (int nt = 0; nt < 4; nt++)
            #pragma unroll
            for (int r = 0; r < 4; r++) acci[mt][nt][r] = 0;
    #pragma unroll
    for (int m = 0; m < 4; m++)
        #pragma unroll
        for (int c = 0; c < 8; c++) accd[m][c] = 0;

    // prefetch chunk 0 into stage 0
    cp16(sb + d0, qb + aoff);            cp16(sb + d1, qb + aoff + 16);
    cp16(sb + 16384 + d0, wbi);          cp16(sb + 16384 + d1, wbi + 16);
    cp16(sb + 32768 + d0, wbd);          cp16(sb + 32768 + d1, wbd + 16);
    CP_COMMIT();

    for (int ch = 0; ch < 9; ch++) {
        if (ch < 8) {
            int nc = ch + 1;
            int dh = nc / 3, dw = nc - dh*3;
            int doff = (dh*HP + dw)*CIN;
            uint32_t stg = sb + ((nc & 1) ? STAGE : 0);
            size_t wo = (size_t)nc*COUT*CIN;
            cp16(stg + d0, qb + aoff + doff);      cp16(stg + d1, qb + aoff + doff + 16);
            cp16(stg + 16384 + d0, wbi + wo);      cp16(stg + 16384 + d1, wbi + wo + 16);
            cp16(stg + 32768 + d0, wbd + wo);      cp16(stg + 32768 + d1, wbd + wo + 16);
            CP_COMMIT();
            CP_WAIT(1);
        } else {
            CP_WAIT(0);
        }
        __syncthreads();

        uint32_t stgA = sb + ((ch & 1) ? STAGE : 0);
        uint32_t stgBi = stgA + 16384, stgBd = stgA + 32768;

        #pragma unroll
        for (int ks = 0; ks < 4; ks++) {
            // ---- IMMA stream: couts 0..127 (tensor pipe) ----
            unsigned bf[4][2];
            #pragma unroll
            for (int nt = 0; nt < 4; nt++) {
                uint32_t base = (wn*32 + nt*8 + g)*128 + ks*32 + tg*4;
                bf[nt][0] = lds32(stgBi + SW128(base));
                bf[nt][1] = lds32(stgBi + SW128(base + 16));
            }
            #pragma unroll
            for (int mt = 0; mt < 2; mt++) {
                unsigned af[4];
                uint32_t base = (wm*32 + mt*16 + g)*128 + ks*32 + tg*4;
                af[0] = lds32(stgA + SW128(base));
                af[1] = lds32(stgA + SW128(base + 8*128));
                af[2] = lds32(stgA + SW128(base + 16));
                af[3] = lds32(stgA + SW128(base + 8*128 + 16));
                #pragma unroll
                for (int nt = 0; nt < 4; nt++)
                    mma16832(acci[mt][nt], af, bf[nt]);
            }
            // ---- dp4a stream: couts 128..255 (fma pipe), same A tile ----
            #pragma unroll
            for (int kw2 = 0; kw2 < 8; kw2++) {
                int k4 = (ks*8 + kw2) * 4;
                int xv[4], wv[8];
                #pragma unroll
                for (int m = 0; m < 4; m++)
                    xv[m] = (int)lds32(stgA + SW128((wm*32 + 8*m + pl)*128 + k4));
                #pragma unroll
                for (int c = 0; c < 8; c++)
                    wv[c] = (int)lds32(stgBd + SW128((wn*32 + cl + 4*c)*128 + k4));
                #pragma unroll
                for (int m = 0; m < 4; m++)
                    #pragma unroll
                    for (int c = 0; c < 8; c++)
                        accd[m][c] = __dp4a(xv[m], wv[c], accd[m][c]);
            }
        }
        __syncthreads();
    }

    // ---- epilogue: both halves via [co][133] float staging, coalesced stores
    float dq = g_dq;
    int px_r = tid & 127, coi = tid >> 7;       // readout: 4 co rows per iter
    bool pv = (p0 + px_r) < NPIX;
    float* ob = out + (size_t)bimg*COUT*NPIX + p0 + px_r;

    // phase 1: IMMA accs -> s_f (co 0..127) -> gmem
    #pragma unroll
    for (int mt = 0; mt < 2; mt++)
        #pragma unroll
        for (int nt = 0; nt < 4; nt++)
            #pragma unroll
            for (int r = 0; r < 4; r++) {
                int co = wn*32 + nt*8 + tg*2 + (r & 1);
                int px = wm*32 + mt*16 + g + ((r >> 1) ? 8 : 0);
                s_f[co*133 + px] = (float)acci[mt][nt][r] * dq;
            }
    __syncthreads();
    if (pv) {
        #pragma unroll 8
        for (int it = 0; it < 32; it++) {
            int co = it*4 + coi;
            ob[(size_t)co * NPIX] = s_f[co*133 + px_r] + __ldg(&bias[co]);
        }
    }
    __syncthreads();

    // phase 2: dp4a accs -> s_f (co 128..255) -> gmem
    #pragma unroll
    for (int m = 0; m < 4; m++)
        #pragma unroll
        for (int c = 0; c < 8; c++) {
            int col_ = wn*32 + cl + 4*c;        // local co (0..127)
            int px = wm*32 + 8*m + pl;
            s_f[col_*133 + px] = (float)accd[m][c] * dq;
        }
    __syncthreads();
    if (pv) {
        #pragma unroll 8
        for (int it = 0; it < 32; it++) {
            int col_ = it*4 + coi;
            int co = 128 + col_;
            ob[(size_t)co * NPIX] = s_f[col_*133 + px_r] + __ldg(&bias[co]);
        }
    }
}

// ---------------- launch ------------------------------------------------------
extern "C" void kernel_launch(void* const* d_in, const int* in_sizes, int n_in,
                              void* d_out, int out_size) {
    const float* x    = (const float*)d_in[0];
    const float* wt   = (const float*)d_in[1];
    const float* bias = (const float*)d_in[2];
    float* out = (float*)d_out;

    cudaFuncSetAttribute(k_conv, cudaFuncAttributeMaxDynamicSharedMemorySize, SMEM_TOTAL);

    k_part<<<1088, 256>>>((const float4*)x, (const float4*)wt);   // idx 0
    k_quant_w<<<288, 256>>>(wt);                                  // idx 1
    k_quant_x<<<BATCH*HP, 256>>>(x);                              // idx 2
    dim3 grid(25, BATCH);
    k_conv<<<grid, 512, SMEM_TOTAL>>>(bias, out);                 // idx 3 (ncu)
    (void)in_sizes; (void)n_in; (void)out_size;
}

// round 9
// speedup vs baseline: 1.9616x; 1.6392x over previous
#include <cuda_runtime.h>
#include <cuda_fp16.h>
#include <stdint.h>

#define BATCH 32
#define CIN   128
#define HH    56
#define WW    56
#define COUT  256
#define HP    58
#define NPIX  (HH*WW)            // 3136
#define IMGB  (HP*HP*CIN)        // padded image elements

// ---------------- scratch (device globals) ----------------------------------
__device__ __half g_qx[BATCH*HP*HP*CIN];   // padded NHWC, quantized ints as fp16 (27.5MB)
__device__ __half g_qw[9*COUT*CIN];        // [tap][co][ci] as fp16
__device__ float  g_px[1024];
__device__ float  g_pw[64];
__device__ float  g_scale_x, g_dq;

// ---------------- helpers -----------------------------------------------------
__device__ __forceinline__ uint32_t smem_u32(const void* p) {
    uint32_t a;
    asm("{ .reg .u64 t; cvta.to.shared.u64 t, %1; cvt.u32.u64 %0, t; }" : "=r"(a) : "l"(p));
    return a;
}
#define SW128(o) ((o) ^ (((o) >> 3) & 0x70))

__device__ __forceinline__ void cp16(uint32_t dst, const void* src) {
    asm volatile("cp.async.cg.shared.global [%0], [%1], 16;" :: "r"(dst), "l"(src) : "memory");
}
#define CP_COMMIT()  asm volatile("cp.async.commit_group;" ::: "memory")
#define CP_WAIT(n)   asm volatile("cp.async.wait_group %0;" :: "n"(n) : "memory")

__device__ __forceinline__ unsigned lds32(uint32_t a) {
    unsigned v; asm volatile("ld.shared.b32 %0, [%1];" : "=r"(v) : "r"(a)); return v;
}

// fp16 HMMA: m16n8k16, A row-major, B col-major, f32 accumulate
__device__ __forceinline__ void hmma16816(float* d, const unsigned* a, const unsigned* b) {
    asm volatile("mma.sync.aligned.m16n8k16.row.col.f32.f16.f16.f32 "
        "{%0,%1,%2,%3}, {%4,%5,%6,%7}, {%8,%9}, {%0,%1,%2,%3};"
        : "+f"(d[0]), "+f"(d[1]), "+f"(d[2]), "+f"(d[3])
        : "r"(a[0]), "r"(a[1]), "r"(a[2]), "r"(a[3]), "r"(b[0]), "r"(b[1]));
}

__device__ __forceinline__ float warp_red_max(float m) {
    #pragma unroll
    for (int o = 16; o; o >>= 1) m = fmaxf(m, __shfl_xor_sync(0xffffffffu, m, o));
    return m;
}

// ---------------- 0: partial amax --------------------------------------------
__global__ void k_part(const float4* __restrict__ x, const float4* __restrict__ w) {
    int blk = blockIdx.x;
    const float4* p; int n4, stride, start;
    if (blk < 1024) { p = x; n4 = BATCH*CIN*HH*WW/4; start = blk*256 + threadIdx.x; stride = 1024*256; }
    else            { p = w; n4 = COUT*CIN*9/4;      start = (blk-1024)*256 + threadIdx.x; stride = 64*256; }
    float m = 0.f;
    for (int i = start; i < n4; i += stride) {
        float4 v = p[i];
        m = fmaxf(m, fmaxf(fmaxf(fabsf(v.x), fabsf(v.y)), fmaxf(fabsf(v.z), fabsf(v.w))));
    }
    m = warp_red_max(m);
    __shared__ float sm[8];
    int lane = threadIdx.x & 31, wid = threadIdx.x >> 5;
    if (lane == 0) sm[wid] = m;
    __syncthreads();
    if (wid == 0) {
        m = (lane < 8) ? sm[lane] : 0.f;
        m = warp_red_max(m);
        if (lane == 0) { if (blk < 1024) g_px[blk] = m; else g_pw[blk-1024] = m; }
    }
}

// ---------------- 1: finalize scales + quantize weights (store fp16) ---------
__global__ void k_quant_w(const float* __restrict__ wt) {
    __shared__ float s_sw;
    {
        float mx = 0.f, mw = 0.f;
        for (int i = threadIdx.x; i < 1024; i += blockDim.x) mx = fmaxf(mx, g_px[i]);
        if (threadIdx.x < 64) mw = g_pw[threadIdx.x];
        mx = warp_red_max(mx); mw = warp_red_max(mw);
        __shared__ float smx[8], smw[8];
        int lane = threadIdx.x & 31, wid = threadIdx.x >> 5;
        if (lane == 0) { smx[wid] = mx; smw[wid] = mw; }
        __syncthreads();
        if (threadIdx.x == 0) {
            float ax = 0.f, aw = 0.f;
            #pragma unroll
            for (int i = 0; i < 8; i++) { ax = fmaxf(ax, smx[i]); aw = fmaxf(aw, smw[i]); }
            float sx = __fdiv_rn(127.0f, ax);
            float sw = __fdiv_rn(127.0f, aw);
            s_sw = sw;
            if (blockIdx.x == 0) {
                g_scale_x = sx;
                g_dq = __fdiv_rn(1.0f, __fmul_rn(sx, sw));
            }
        }
        __syncthreads();
    }
    float sc = s_sw;
    const int n = 9*COUT*CIN;
    for (int o = blockIdx.x*blockDim.x + threadIdx.x; o < n; o += gridDim.x*blockDim.x) {
        int ci  = o & 127;
        int co  = (o >> 7) & 255;
        int tap = o >> 15;
        float q = rintf(wt[(co*CIN + ci)*9 + tap] * sc);
        q = fminf(fmaxf(q, -127.f), 127.f);
        g_qw[o] = __float2half_rn(q);       // |q|<=127: exact in fp16
    }
}

// ---------------- 2: quantize x into padded NHWC (store fp16) -----------------
__global__ void k_quant_x(const float* __restrict__ x) {
    int b = blockIdx.x / HP, hp = blockIdx.x % HP;
    __half* dst = g_qx + ((size_t)b*HP + hp)*HP*CIN;
    if (hp == 0 || hp == HP-1) {
        for (int e = threadIdx.x; e < HP*CIN/8; e += blockDim.x)
            ((int4*)dst)[e] = make_int4(0,0,0,0);   // fp16 zero bits
        return;
    }
    int h = hp - 1;
    __shared__ __half s[CIN][60];
    float sc = g_scale_x;
    const float* base = x + ((size_t)b*CIN*HH + h)*WW;
    for (int e = threadIdx.x; e < CIN*WW; e += blockDim.x) {
        int c = e / WW, w = e - c*WW;
        float q = rintf(base[(size_t)c*HH*WW + w] * sc);
        q = fminf(fmaxf(q, -127.f), 127.f);
        s[c][w] = __float2half_rn(q);
    }
    __syncthreads();
    for (int e = threadIdx.x; e < HP*CIN; e += blockDim.x) {
        int wp = e >> 7, c = e & 127;
        dst[e] = (wp == 0 || wp == HP-1) ? __float2half_rn(0.f) : s[c][wp-1];
    }
}

// ---------------- 3: fp16 HMMA implicit-GEMM conv -----------------------------
// CTA: 128 px x 128 co, 256 thr = 8 warps (4m x 2n); warp tile 32px x 64co.
// K = 9 taps x 128 ci, chunked at 64 ci (fp16 row = 128B, SW128 applies).
// 18 chunks, cp.async double-buffered; stage = A 16KB + B 16KB.
#define STAGE 32768
#define SMEM_TOTAL 65536

__global__ void __launch_bounds__(256, 2) k_conv(const float* __restrict__ bias,
                                                 float* __restrict__ out) {
    extern __shared__ char smem[];
    uint32_t sb = smem_u32(smem);
    float* s_out = (float*)smem;

    int tid = threadIdx.x;
    int wid = tid >> 5, lane = tid & 31;
    int wm = wid & 3, wn = wid >> 2;            // 4 x 2 warp grid
    int g = lane >> 2, tg = lane & 3;

    int tile   = blockIdx.x;                    // 0..24
    int coBase = blockIdx.y << 7;               // 0 or 128
    int bimg   = blockIdx.z;
    int p0 = tile * 128;

    // producer: thread t loads row r = t>>1, 4x16B segs starting at (t&1)*4
    int r = tid >> 1, s4 = (tid & 1) << 2;
    int p = min(p0 + r, NPIX-1);
    int ph = p / WW, pw = p - ph*WW;
    const __half* qb = g_qx + (size_t)bimg * IMGB;
    const __half* abase = qb + (ph*HP + pw)*CIN;
    const __half* wbase = g_qw + (size_t)(coBase + r)*CIN;
    uint32_t dA[4], dB[4];
    #pragma unroll
    for (int i = 0; i < 4; i++) {
        uint32_t o = SW128((uint32_t)(r*128 + (s4+i)*16));
        dA[i] = o; dB[i] = 16384 + o;
    }

    float acc[2][8][4];
    #pragma unroll
    for (int mt = 0; mt < 2; mt++)
        #pragma unroll
        for (int nt = 0; nt < 8; nt++)
            #pragma unroll
            for (int q = 0; q < 4; q++) acc[mt][nt][q] = 0.f;

    // prefetch chunk 0 (tap 0, khalf 0) into stage 0
    #pragma unroll
    for (int i = 0; i < 4; i++) {
        cp16(sb + dA[i], abase + (s4+i)*8);
        cp16(sb + dB[i], wbase + (s4+i)*8);
    }
    CP_COMMIT();

    for (int ch = 0; ch < 18; ch++) {
        if (ch < 17) {
            int nc = ch + 1;
            int tap = nc >> 1, kh2 = nc & 1;
            int dh = tap / 3, dw = tap - dh*3;
            const __half* as = abase + (dh*HP + dw)*CIN + kh2*64;
            const __half* ws = wbase + (size_t)tap*COUT*CIN + kh2*64;
            uint32_t stg = sb + ((nc & 1) ? STAGE : 0);
            #pragma unroll
            for (int i = 0; i < 4; i++) {
                cp16(stg + dA[i], as + (s4+i)*8);
                cp16(stg + dB[i], ws + (s4+i)*8);
            }
            CP_COMMIT();
            CP_WAIT(1);
        } else {
            CP_WAIT(0);
        }
        __syncthreads();

        uint32_t stgA = sb + ((ch & 1) ? STAGE : 0), stgB = stgA + 16384;
        #pragma unroll
        for (int ks = 0; ks < 4; ks++) {        // 4 x k16 per 64-ci chunk
            unsigned bf[8][2];
            #pragma unroll
            for (int nt = 0; nt < 8; nt++) {
                uint32_t base = (wn*64 + nt*8 + g)*128 + ks*32 + tg*4;
                bf[nt][0] = lds32(stgB + SW128(base));
                bf[nt][1] = lds32(stgB + SW128(base + 16));
            }
            #pragma unroll
            for (int mt = 0; mt < 2; mt++) {
                unsigned af[4];
                uint32_t base = (wm*32 + mt*16 + g)*128 + ks*32 + tg*4;
                af[0] = lds32(stgA + SW128(base));
                af[1] = lds32(stgA + SW128(base + 8*128));
                af[2] = lds32(stgA + SW128(base + 16));
                af[3] = lds32(stgA + SW128(base + 8*128 + 16));
                #pragma unroll
                for (int nt = 0; nt < 8; nt++)
                    hmma16816(acc[mt][nt], af, bf[nt]);
            }
        }
        __syncthreads();
    }

    // ---- epilogue: stage [64co][132px] in smem, coalesced dequant+bias stores
    float dq = g_dq;
    int rr = tid >> 7;              // 0..1
    int px = tid & 127;
    bool pv = (p0 + px) < NPIX;
    float* obase = out + ((size_t)bimg*COUT + coBase)*NPIX + p0 + px;

    #pragma unroll
    for (int pass = 0; pass < 2; pass++) {
        if (wn == pass) {
            #pragma unroll
            for (int mt = 0; mt < 2; mt++) {
                int px0 = wm*32 + mt*16 + g;
                #pragma unroll
                for (int nt = 0; nt < 8; nt++) {
                    int cl = nt*8 + tg*2;
                    s_out[cl*132 + px0]         = acc[mt][nt][0] * dq;
                    s_out[(cl+1)*132 + px0]     = acc[mt][nt][1] * dq;
                    s_out[cl*132 + px0 + 8]     = acc[mt][nt][2] * dq;
                    s_out[(cl+1)*132 + px0 + 8] = acc[mt][nt][3] * dq;
                }
            }
        }
        __syncthreads();
        if (pv) {
            #pragma unroll 8
            for (int it = 0; it < 32; it++) {
                int row = it*2 + rr;
                int co = pass*64 + row;
                obase[(size_t)co * NPIX] = s_out[row*132 + px] + __ldg(&bias[coBase + co]);
            }
        }
        __syncthreads();
    }
}

// ---------------- launch ------------------------------------------------------
extern "C" void kernel_launch(void* const* d_in, const int* in_sizes, int n_in,
                              void* d_out, int out_size) {
    const float* x    = (const float*)d_in[0];
    const float* wt   = (const float*)d_in[1];
    const float* bias = (const float*)d_in[2];
    float* out = (float*)d_out;

    cudaFuncSetAttribute(k_conv, cudaFuncAttributeMaxDynamicSharedMemorySize, SMEM_TOTAL);

    k_part<<<1088, 256>>>((const float4*)x, (const float4*)wt);   // idx 0
    k_quant_w<<<288, 256>>>(wt);                                  // idx 1
    k_quant_x<<<BATCH*HP, 256>>>(x);                              // idx 2
    dim3 grid(25, 2, BATCH);
    k_conv<<<grid, 256, SMEM_TOTAL>>>(bias, out);                 // idx 3 (ncu)
    (void)in_sizes; (void)n_in; (void)out_size;
}